// round 17
// baseline (speedup 1.0000x reference)
#include <cuda_runtime.h>
#include <cstdint>

#define B_DIM 16
#define T_DIM 8
#define C_DIM 64
#define P_DIM 2048
#define ROWS  (B_DIM * T_DIM * C_DIM)     // 8192 destination rows
#define TOTAL_ELEMS (ROWS * P_DIM)        // 16777216
#define NTHR 256
#define ROW_BYTES (P_DIM * 4)             // 8192 bytes per row

// Partials + completion counter. No device-side allocation.
__device__ float4 g_part[ROWS];
__device__ unsigned int g_cnt = 0;

__device__ __forceinline__ uint32_t smem_u32(const void* p) {
    uint32_t a;
    asm("{ .reg .u64 t; cvta.to.shared.u64 t, %1; cvt.u32.u64 %0, t; }"
        : "=r"(a) : "l"(p));
    return a;
}

// R6 main (best measured: ~52.8us) + fused last-block reduction.
// Counter+reset pattern validated in-harness by R16's final kernel.
__global__ __launch_bounds__(NTHR) void attnloss_kernel(
    const float* __restrict__ x,
    const float* __restrict__ attn,
    const float* __restrict__ noise,
    const int* __restrict__ mask,    // bool promoted to 4-byte words
    const int* __restrict__ pB1, const int* __restrict__ pT1,
    const int* __restrict__ pC1, const int* __restrict__ pP1,
    const int* __restrict__ pB2, const int* __restrict__ pT2,
    const int* __restrict__ pC2, const int* __restrict__ pP2,
    const int* __restrict__ pB3, const int* __restrict__ pT3,
    const int* __restrict__ pC3, const int* __restrict__ pP3,
    float* __restrict__ out)
{
    __shared__ __align__(128) float sm[3 * P_DIM];   // 24 KB: three source rows
    __shared__ __align__(8) uint64_t mbar;

    const float* const sm1 = sm;
    const float* const sm2 = sm + P_DIM;
    const float* const sm3 = sm + 2 * P_DIM;

    const int tid = threadIdx.x;
    const int blk = blockIdx.x;              // destination row id
    const uint32_t mbar_a = smem_u32(&mbar);

    if (tid == 0) {
        asm volatile("mbarrier.init.shared.b64 [%0], 1;" :: "r"(mbar_a) : "memory");
    }
    __syncthreads();

    if (tid == 0) {
        const int c = blk & (C_DIM - 1);
        const int t = (blk >> 6) & (T_DIM - 1);
        const int b = blk >> 9;
        // Source row bases (contiguous 8 KB rows of x). 32-bit math: max < 2^24.
        const int rb1 = ((((__ldg(pB1 + b) << 3) + __ldg(pT1 + t)) << 6) + __ldg(pC1 + c)) << 11;
        const int rb2 = ((((__ldg(pB2 + b) << 3) + __ldg(pT2 + t)) << 6) + __ldg(pC2 + c)) << 11;
        const int rb3 = ((((__ldg(pB3 + b) << 3) + __ldg(pT3 + t)) << 6) + __ldg(pC3 + c)) << 11;

        asm volatile("mbarrier.arrive.expect_tx.shared.b64 _, [%0], %1;"
                     :: "r"(mbar_a), "r"(3 * ROW_BYTES) : "memory");
        asm volatile("cp.async.bulk.shared::cta.global.mbarrier::complete_tx::bytes [%0], [%1], %2, [%3];"
                     :: "r"(smem_u32(sm1)), "l"(x + rb1), "r"(ROW_BYTES), "r"(mbar_a) : "memory");
        asm volatile("cp.async.bulk.shared::cta.global.mbarrier::complete_tx::bytes [%0], [%1], %2, [%3];"
                     :: "r"(smem_u32(sm2)), "l"(x + rb2), "r"(ROW_BYTES), "r"(mbar_a) : "memory");
        asm volatile("cp.async.bulk.shared::cta.global.mbarrier::complete_tx::bytes [%0], [%1], %2, [%3];"
                     :: "r"(smem_u32(sm3)), "l"(x + rb3), "r"(ROW_BYTES), "r"(mbar_a) : "memory");
    }

    // Batch ALL streaming loads up front (max MLP, in flight across the wait).
    float4 x4[2], a4[2], n4[2];
    int4 m4[2], pp1[2], pp2[2], pp3[2];
    #pragma unroll
    for (int j = 0; j < 2; j++) {
        const int vloc = j * NTHR + tid;         // 0..511, warp-contiguous
        const int gv = (blk << 9) + vloc;
        x4[j] = __ldg((const float4*)x + gv);            // L2-resident
        a4[j] = __ldcs((const float4*)attn + gv);        // stream
        n4[j] = __ldcs((const float4*)noise + gv);       // stream
        m4[j] = __ldcs((const int4*)mask + gv);          // stream
        pp1[j] = __ldg((const int4*)pP1 + vloc);         // L1-hot tables
        pp2[j] = __ldg((const int4*)pP2 + vloc);
        pp3[j] = __ldg((const int4*)pP3 + vloc);
    }

    // Wait for the three source rows (acquire orders the LDS gathers below).
    {
        uint32_t done;
        asm volatile(
            "{\n\t.reg .pred p;\n\t"
            "mbarrier.try_wait.parity.acquire.cta.shared::cta.b64 p, [%1], 0;\n\t"
            "selp.b32 %0, 1, 0, p;\n\t}"
            : "=r"(done) : "r"(mbar_a) : "memory");
        if (!done) {
            asm volatile(
                "{\n\t.reg .pred P1;\n\t"
                "WAIT_LOOP_%=:\n\t"
                "mbarrier.try_wait.parity.acquire.cta.shared::cta.b64 P1, [%0], 0, 0x989680;\n\t"
                "@P1 bra.uni WAIT_DONE_%=;\n\t"
                "bra.uni WAIT_LOOP_%=;\n\t"
                "WAIT_DONE_%=:\n\t}"
                :: "r"(mbar_a) : "memory");
        }
    }

    float s0 = 0.f, s1a = 0.f, s2a = 0.f, s3a = 0.f;

    #pragma unroll
    for (int j = 0; j < 2; j++) {
        s0 += (m4[j].x ? a4[j].x * n4[j].x * n4[j].x : 0.f)
            + (m4[j].y ? a4[j].y * n4[j].y * n4[j].y : 0.f)
            + (m4[j].z ? a4[j].z * n4[j].z * n4[j].z : 0.f)
            + (m4[j].w ? a4[j].w * n4[j].w * n4[j].w : 0.f);

        float d;
        d = x4[j].x - sm1[pp1[j].x]; s1a += a4[j].x * d * d;
        d = x4[j].y - sm1[pp1[j].y]; s1a += a4[j].y * d * d;
        d = x4[j].z - sm1[pp1[j].z]; s1a += a4[j].z * d * d;
        d = x4[j].w - sm1[pp1[j].w]; s1a += a4[j].w * d * d;

        d = x4[j].x - sm2[pp2[j].x]; s2a += a4[j].x * d * d;
        d = x4[j].y - sm2[pp2[j].y]; s2a += a4[j].y * d * d;
        d = x4[j].z - sm2[pp2[j].z]; s2a += a4[j].z * d * d;
        d = x4[j].w - sm2[pp2[j].w]; s2a += a4[j].w * d * d;

        d = x4[j].x - sm3[pp3[j].x]; s3a += a4[j].x * d * d;
        d = x4[j].y - sm3[pp3[j].y]; s3a += a4[j].y * d * d;
        d = x4[j].z - sm3[pp3[j].z]; s3a += a4[j].z * d * d;
        d = x4[j].w - sm3[pp3[j].w]; s3a += a4[j].w * d * d;
    }

    // Block reduction (deterministic tree)
    #pragma unroll
    for (int o = 16; o > 0; o >>= 1) {
        s0  += __shfl_down_sync(0xffffffffu, s0,  o);
        s1a += __shfl_down_sync(0xffffffffu, s1a, o);
        s2a += __shfl_down_sync(0xffffffffu, s2a, o);
        s3a += __shfl_down_sync(0xffffffffu, s3a, o);
    }
    __shared__ float4 shp[NTHR / 32];
    const int w = tid >> 5;
    if ((tid & 31) == 0) shp[w] = make_float4(s0, s1a, s2a, s3a);
    __syncthreads();

    if (tid == 0) {
        float4 acc = shp[0];
        #pragma unroll
        for (int k = 1; k < NTHR / 32; k++) {
            acc.x += shp[k].x; acc.y += shp[k].y;
            acc.z += shp[k].z; acc.w += shp[k].w;
        }
        g_part[blk] = acc;
    }

    // ---- fused final reduction: last-arriving CTA does the deterministic
    //      tree over all 8192 partials (result independent of which CTA). ----
    __shared__ bool isLast;
    __threadfence();
    if (tid == 0)
        isLast = (atomicAdd(&g_cnt, 1u) == (unsigned)(gridDim.x - 1));
    __syncthreads();

    if (isLast) {
        float r0 = 0.f, r1 = 0.f, r2 = 0.f, r3 = 0.f;
        // 8192 partials / 256 threads = 32 each; unrolled for MLP. __ldcg:
        // L2 path (partials written by other SMs; writers fenced above).
        #pragma unroll
        for (int u = 0; u < ROWS / NTHR; u++) {
            const float4 p = __ldcg(&g_part[u * NTHR + tid]);
            r0 += p.x; r1 += p.y; r2 += p.z; r3 += p.w;
        }
        #pragma unroll
        for (int o = 16; o > 0; o >>= 1) {
            r0 += __shfl_down_sync(0xffffffffu, r0, o);
            r1 += __shfl_down_sync(0xffffffffu, r1, o);
            r2 += __shfl_down_sync(0xffffffffu, r2, o);
            r3 += __shfl_down_sync(0xffffffffu, r3, o);
        }
        if ((tid & 31) == 0) shp[w] = make_float4(r0, r1, r2, r3);
        __syncthreads();
        if (tid == 0) {
            float4 r = shp[0];
            #pragma unroll
            for (int k = 1; k < NTHR / 32; k++) {
                r.x += shp[k].x; r.y += shp[k].y;
                r.z += shp[k].z; r.w += shp[k].w;
            }
            const float inv = 1.0f / (float)TOTAL_ELEMS;
            const float pos = r.x * inv;
            const float n1  = r.y * inv;
            const float n2  = r.z * inv;
            const float n3  = r.w * inv;
            // TEMP = 1:  loss = -pos + log(exp(n1)+exp(n2)+exp(n3))
            out[0] = -pos + logf(expf(n1) + expf(n2) + expf(n3));
            g_cnt = 0;   // reset for next graph replay (proven in R16)
        }
    }
}

extern "C" void kernel_launch(void* const* d_in, const int* in_sizes, int n_in,
                              void* d_out, int out_size)
{
    const float* x     = (const float*)d_in[0];
    const float* attn  = (const float*)d_in[1];
    const float* noise = (const float*)d_in[2];
    const int*   mask  = (const int*)d_in[3];
    const int* pB1 = (const int*)d_in[4];
    const int* pT1 = (const int*)d_in[5];
    const int* pC1 = (const int*)d_in[6];
    const int* pP1 = (const int*)d_in[7];
    const int* pB2 = (const int*)d_in[8];
    const int* pT2 = (const int*)d_in[9];
    const int* pC2 = (const int*)d_in[10];
    const int* pP2 = (const int*)d_in[11];
    const int* pB3 = (const int*)d_in[12];
    const int* pT3 = (const int*)d_in[13];
    const int* pC3 = (const int*)d_in[14];
    const int* pP3 = (const int*)d_in[15];

    attnloss_kernel<<<ROWS, NTHR>>>(
        x, attn, noise, mask,
        pB1, pT1, pC1, pP1,
        pB2, pT2, pC2, pP2,
        pB3, pT3, pC3, pP3,
        (float*)d_out);
}